// round 2
// baseline (speedup 1.0000x reference)
#include <cuda_runtime.h>

// LengthRegulator: out[b, f, :] = xs[b, searchsorted(cumsum(ds[b]), f, right), :]
//                  (0 if f >= total), with all-zero ds rows treated as all-ones.
// B=32, T=512, D=384, MAX_FRAMES=2048.

#define BB 32
#define TT 512
#define DD 384
#define MF 2048
#define D4 (DD / 4)   // 96 float4 per row

// Frame -> source-token index map; -1 means padding (write zeros).
__device__ int g_idx[BB * MF];

// ---------------------------------------------------------------------------
// Kernel A: per-batch inclusive scan of durations + scatter frame->token map.
// One block per batch row, 512 threads (one per token).
// The ds buffer dtype (int32 vs int64) is detected at runtime: durations are
// in [0,4], so an int64 buffer has every odd int32 word == 0. We sample 256
// odd words; for genuine int32 data P(all zero) = 0.2^256 ~ 0.
// ---------------------------------------------------------------------------
__global__ void __launch_bounds__(TT) lr_scan_kernel(const int* __restrict__ ds32) {
    const int b = blockIdx.x;
    const int t = threadIdx.x;

    __shared__ int s[TT];

    // --- dtype detection (identical result in every block) ---
    int bad = 0;
    if (t < 256) {
        // sample odd int32 positions spread across the first 16384 words
        int pos = 2 * (t * 32) + 1;      // 1, 65, ..., 16321  (< 16384)
        if (ds32[pos] != 0) bad = 1;
    }
    const bool is64 = (__syncthreads_or(bad) == 0);

    int d;
    if (is64) {
        d = (int)((const long long*)ds32)[b * TT + t];
    } else {
        d = ds32[b * TT + t];
    }

    s[t] = d;
    __syncthreads();

    // Hillis-Steele inclusive scan over 512 elements (9 steps).
#pragma unroll
    for (int off = 1; off < TT; off <<= 1) {
        int v = s[t];
        int add = (t >= off) ? s[t - off] : 0;
        __syncthreads();
        s[t] = v + add;
        __syncthreads();
    }

    const int total = s[TT - 1];

    // Initialize all MF frames of this batch to -1 (padding).
#pragma unroll
    for (int k = 0; k < MF / TT; k++)
        g_idx[b * MF + t + k * TT] = -1;
    __syncthreads();   // order init before scatter within the block

    if (total == 0) {
        // all-zero row => durations become all 1 => identity map for f < T
        g_idx[b * MF + t] = t;
    } else {
        const int end   = s[t];
        const int start = end - d;
        for (int f = start; f < end; f++)
            g_idx[b * MF + f] = t;
    }
}

// ---------------------------------------------------------------------------
// Kernel B: bandwidth mover. Grid-stride over float4 elements of the output.
// 96 consecutive threads share one g_idx lookup (L1-resident).
// ---------------------------------------------------------------------------
__global__ void __launch_bounds__(256) lr_gather_kernel(const float4* __restrict__ xs,
                                                        float4* __restrict__ out) {
    const int total4 = BB * MF * D4;          // 6,291,456
    int i = blockIdx.x * blockDim.x + threadIdx.x;
    if (i >= total4) return;

    const int per_b = MF * D4;
    const int b   = i / per_b;
    const int rem = i - b * per_b;
    const int f   = rem / D4;
    const int c   = rem - f * D4;

    const int idx = g_idx[b * MF + f];

    float4 v;
    if (idx < 0) {
        v = make_float4(0.f, 0.f, 0.f, 0.f);
    } else {
        v = __ldg(&xs[(b * TT + idx) * D4 + c]);
    }
    out[i] = v;
}

// ---------------------------------------------------------------------------
extern "C" void kernel_launch(void* const* d_in, const int* in_sizes, int n_in,
                              void* d_out, int out_size) {
    // Select pointers by element count, not position:
    //   xs: 32*512*384 = 6,291,456 * 4? no -> 12,582,912? compute: 32*512*384 = 6,291,456? 
    //   32*512 = 16,384 tokens; *384 = 6,291,456 floats. ds: 16,384 elems.
    const void* p0 = d_in[0];
    const void* p1 = d_in[1];
    const float* xs;
    const int* ds;
    if (in_sizes[0] > in_sizes[1]) {
        xs = (const float*)p0;  ds = (const int*)p1;
    } else {
        xs = (const float*)p1;  ds = (const int*)p0;
    }
    float4* out = (float4*)d_out;

    lr_scan_kernel<<<BB, TT>>>(ds);

    const int total4 = BB * MF * D4;
    const int threads = 256;
    const int blocks = (total4 + threads - 1) / threads;
    lr_gather_kernel<<<blocks, threads>>>((const float4*)xs, out);
}

// round 3
// speedup vs baseline: 1.1404x; 1.1404x over previous
#include <cuda_runtime.h>

// LengthRegulator: out[b, f, :] = xs[b, searchsorted(cumsum(ds[b]), f, right), :]
//                  (0 if f >= total), all-zero ds rows treated as all-ones.
// B=32, T=512, D=384, MAX_FRAMES=2048.

#define BB 32
#define TT 512
#define DD 384
#define MF 2048
#define D4 (DD / 4)      // 96 float4 per row
#define UNROLL 4
#define GTHREADS 256

// Frame -> source-token index map; -1 means padding (write zeros).
__device__ int g_idx[BB * MF];

// ---------------------------------------------------------------------------
// Kernel A: per-batch inclusive scan (warp-shuffle based, 2 barriers) +
// scatter frame->token map. One block per batch row, 512 threads.
// ds dtype (int32 vs int64) detected at runtime: durations are in [0,4], so
// an int64 buffer has every odd int32 word == 0. P(false positive) = 0.2^256.
// ---------------------------------------------------------------------------
__global__ void __launch_bounds__(TT) lr_scan_kernel(const int* __restrict__ ds32) {
    const int b    = blockIdx.x;
    const int t    = threadIdx.x;
    const int lane = t & 31;
    const int wid  = t >> 5;           // 16 warps

    __shared__ int s_warp[16];
    __shared__ int s_off[17];          // exclusive offsets + block total

    // --- dtype detection (identical result in every block, no barrier needed:
    //     the warp-uniform result is computed per-warp via ballot) ---
    int pos = 2 * (t * 32) + 1;        // odd words spread over first 32768 ints
    int bad = (t < 256) ? (ds32[pos & 16383] != 0) : 0;
    // reduce across block with the first barrier below via shared flag:
    __shared__ int s_bad;
    if (t == 0) s_bad = 0;
    // (ordering: s_bad init races with the atomicOr below only within this
    //  block; use syncthreads)
    __syncthreads();
    if (bad) atomicOr(&s_bad, 1);

    // Init this batch's g_idx to -1 while the flag settles (before barrier 2).
    ((int4*)g_idx)[b * (MF / 4) + t] = make_int4(-1, -1, -1, -1);

    __syncthreads();
    const bool is64 = (s_bad == 0);

    int d = is64 ? (int)((const long long*)ds32)[b * TT + t]
                 : ds32[b * TT + t];

    // --- warp inclusive scan (no barriers) ---
    int v = d;
#pragma unroll
    for (int off = 1; off < 32; off <<= 1) {
        int n = __shfl_up_sync(0xFFFFFFFFu, v, off);
        if (lane >= off) v += n;
    }
    if (lane == 31) s_warp[wid] = v;
    __syncthreads();

    if (wid == 0) {
        int w = (lane < 16) ? s_warp[lane] : 0;
#pragma unroll
        for (int off = 1; off < 16; off <<= 1) {
            int n = __shfl_up_sync(0xFFFFFFFFu, w, off);
            if (lane >= off) w += n;
        }
        if (lane < 16) s_off[lane + 1] = w;   // exclusive offset for warp lane+1... (inclusive at lane)
        if (lane == 0) s_off[0] = 0;
    }
    __syncthreads();

    const int cum   = v + s_off[wid];      // inclusive cumsum at token t
    const int total = s_off[16];           // block total

    if (total == 0) {
        // all-zero row => durations all 1 => identity map for f < T
        g_idx[b * MF + t] = t;
    } else {
        const int end   = cum;
        const int start = cum - d;
        for (int f = start; f < end; f++)
            g_idx[b * MF + f] = t;
    }
}

// ---------------------------------------------------------------------------
// Kernel B: bandwidth mover, 4 float4 per thread for MLP.
// total4 = 6,291,456 = 6144 blocks * 256 threads * 4 — exact, no tail check.
// ---------------------------------------------------------------------------
__global__ void __launch_bounds__(GTHREADS)
lr_gather_kernel(const float4* __restrict__ xs, float4* __restrict__ out) {
    const int base = blockIdx.x * (GTHREADS * UNROLL) + threadIdx.x;
    const int per_b = MF * D4;

    int idx[UNROLL];
    int ii[UNROLL];
#pragma unroll
    for (int k = 0; k < UNROLL; k++) {
        const int i = base + k * GTHREADS;
        ii[k] = i;
        const int b   = i / per_b;
        const int rem = i - b * per_b;
        const int f   = rem / D4;
        idx[k] = g_idx[b * MF + f] ;           // L1-resident map
        // encode b alongside: re-derive below
    }

    float4 v[UNROLL];
#pragma unroll
    for (int k = 0; k < UNROLL; k++) {
        const int i = ii[k];
        const int b   = i / per_b;
        const int rem = i - b * per_b;
        const int f   = rem / D4;
        const int c   = rem - f * D4;
        if (idx[k] < 0) {
            v[k] = make_float4(0.f, 0.f, 0.f, 0.f);
        } else {
            v[k] = __ldg(&xs[(b * TT + idx[k]) * D4 + c]);
        }
    }

#pragma unroll
    for (int k = 0; k < UNROLL; k++)
        out[ii[k]] = v[k];
}

// ---------------------------------------------------------------------------
extern "C" void kernel_launch(void* const* d_in, const int* in_sizes, int n_in,
                              void* d_out, int out_size) {
    // Select pointers by element count (xs: 6,291,456 floats; ds: 16,384).
    const float* xs;
    const int* ds;
    if (in_sizes[0] > in_sizes[1]) {
        xs = (const float*)d_in[0];  ds = (const int*)d_in[1];
    } else {
        xs = (const float*)d_in[1];  ds = (const int*)d_in[0];
    }
    float4* out = (float4*)d_out;

    lr_scan_kernel<<<BB, TT>>>(ds);

    const int total4 = BB * MF * D4;                    // 6,291,456
    const int blocks = total4 / (GTHREADS * UNROLL);    // 6144 exact
    lr_gather_kernel<<<blocks, GTHREADS>>>((const float4*)xs, out);
}

// round 4
// speedup vs baseline: 1.1511x; 1.0094x over previous
#include <cuda_runtime.h>

// LengthRegulator (fused single kernel):
//   out[b, f, :] = xs[b, searchsorted(cumsum(ds[b]), f, right), :]
//   (0 if f >= total); all-zero ds rows treated as all-ones.
// B=32, T=512, D=384, MAX_FRAMES=2048.

#define BB 32
#define TT 512
#define DD 384
#define MF 2048
#define D4 (DD / 4)            // 96 float4 per frame
#define FPB 64                 // frames per block
#define CHUNKS (MF / FPB)      // 32 chunks per batch
#define NTHR 256
#define ELEMS (FPB * D4)       // 6144 float4 per block
#define PER_THR (ELEMS / NTHR) // 24
#define MLP 8                  // loads in flight per thread
#define ITERS (PER_THR / MLP)  // 3

// ---------------------------------------------------------------------------
// One block = (batch b, frame window [w0, w0+64)).
// Phase 1: redundant per-batch scan of 512 durations (shuffle-based).
// Phase 2: scatter frame->token map for this window into shared.
// Phase 3: gather 6144 float4 with 8-deep load pipelining.
// ---------------------------------------------------------------------------
__global__ void __launch_bounds__(NTHR)
lr_fused_kernel(const float4* __restrict__ xs, const int* __restrict__ ds32,
                float4* __restrict__ out) {
    const int b    = blockIdx.x / CHUNKS;
    const int w0   = (blockIdx.x % CHUNKS) * FPB;
    const int tid  = threadIdx.x;
    const int lane = tid & 31;
    const int wid  = tid >> 5;                 // 8 warps

    __shared__ int s_map[FPB];                 // frame -> token (-1 = pad)
    __shared__ int s_warp[8];
    __shared__ int s_off[9];
    __shared__ int s_bad;

    // --- dtype detection sampling (int64 buffer => all odd int32 words are 0;
    //     durations are in [0,4], P(false positive for int32) = 0.2^256) ---
    if (tid == 0) s_bad = 0;
    const int samp = ds32[(2 * (tid * 64) + 1) & 16383];
    // init pad map
    if (tid < FPB) s_map[tid] = -1;
    __syncthreads();
    if (samp != 0) atomicOr(&s_bad, 1);
    __syncthreads();
    const bool is64 = (s_bad == 0);

    // --- load 2 durations per thread ---
    int d0, d1;
    if (is64) {
        longlong2 p = ((const longlong2*)ds32)[b * (TT / 2) + tid];
        d0 = (int)p.x; d1 = (int)p.y;
    } else {
        int2 p = ((const int2*)ds32)[b * (TT / 2) + tid];
        d0 = p.x; d1 = p.y;
    }

    // --- hierarchical inclusive scan over 512 ---
    int sum = d0 + d1;
    int incl = sum;
#pragma unroll
    for (int off = 1; off < 32; off <<= 1) {
        int n = __shfl_up_sync(0xFFFFFFFFu, incl, off);
        if (lane >= off) incl += n;
    }
    if (lane == 31) s_warp[wid] = incl;
    __syncthreads();
    if (wid == 0) {
        int w = (lane < 8) ? s_warp[lane] : 0;
#pragma unroll
        for (int off = 1; off < 8; off <<= 1) {
            int n = __shfl_up_sync(0xFFFFFFFFu, w, off);
            if (lane >= off) w += n;
        }
        if (lane < 8) s_off[lane + 1] = w;
        if (lane == 0) s_off[0] = 0;
    }
    __syncthreads();

    const int excl  = incl - sum + s_off[wid]; // exclusive prefix at token 2*tid
    const int total = s_off[8];

    // --- scatter into this block's frame window ---
    const int w1 = w0 + FPB;
    if (total == 0) {
        // all-zero row => durations all 1 => identity map for f < T
        if (tid < FPB) {
            int f = w0 + tid;
            s_map[tid] = (f < TT) ? f : -1;
        }
    } else {
        // token 2*tid owns [excl, excl+d0); token 2*tid+1 owns [excl+d0, excl+d0+d1)
        int st = excl, en = excl + d0;
        int lo = st > w0 ? st : w0;
        int hi = en < w1 ? en : w1;
        for (int f = lo; f < hi; f++) s_map[f - w0] = 2 * tid;
        st = en; en += d1;
        lo = st > w0 ? st : w0;
        hi = en < w1 ? en : w1;
        for (int f = lo; f < hi; f++) s_map[f - w0] = 2 * tid + 1;
    }
    __syncthreads();

    // --- gather: 24 float4 per thread, 8 loads in flight ---
    const float4* xsb  = xs  + (size_t)b * TT * D4;
    float4*       outb = out + ((size_t)b * MF + w0) * D4;

#pragma unroll
    for (int it = 0; it < ITERS; it++) {
        const int j0 = it * (NTHR * MLP) + tid;
        float4 v[MLP];
#pragma unroll
        for (int k = 0; k < MLP; k++) {
            const int j = j0 + k * NTHR;       // < 6144
            const int f = j / D4;
            const int c = j - f * D4;
            const int idx = s_map[f];
            if (idx < 0) {
                v[k] = make_float4(0.f, 0.f, 0.f, 0.f);
            } else {
                v[k] = __ldg(&xsb[idx * D4 + c]);
            }
        }
#pragma unroll
        for (int k = 0; k < MLP; k++)
            outb[j0 + k * NTHR] = v[k];
    }
}

// ---------------------------------------------------------------------------
extern "C" void kernel_launch(void* const* d_in, const int* in_sizes, int n_in,
                              void* d_out, int out_size) {
    // Select pointers by element count (xs: 6,291,456 floats; ds: 16,384).
    const float* xs;
    const int* ds;
    if (in_sizes[0] > in_sizes[1]) {
        xs = (const float*)d_in[0];  ds = (const int*)d_in[1];
    } else {
        xs = (const float*)d_in[1];  ds = (const int*)d_in[0];
    }
    float4* out = (float4*)d_out;

    lr_fused_kernel<<<BB * CHUNKS, NTHR>>>((const float4*)xs, ds, out);
}

// round 6
// speedup vs baseline: 1.1663x; 1.0132x over previous
#include <cuda_runtime.h>

// LengthRegulator (fused single kernel):
//   out[b, f, :] = xs[b, searchsorted(cumsum(ds[b]), f, right), :]
//   (0 if f >= total); all-zero ds rows treated as all-ones.
// B=32, T=512, D=384, MAX_FRAMES=2048.

#define BB 32
#define TT 512
#define DD 384
#define MF 2048
#define D4 (DD / 4)            // 96 float4 per frame
#define FPB 64                 // frames per block
#define CHUNKS (MF / FPB)      // 32 chunks per batch
#define NTHR 256
#define ELEMS (FPB * D4)       // 6144 float4 per block
#define PER_THR (ELEMS / NTHR) // 24
#define MLP 8                  // loads in flight per thread
#define ITERS (PER_THR / MLP)  // 3

// ---------------------------------------------------------------------------
// One block = (batch b, frame window [w0, w0+64)).
// Phase 1: redundant per-batch scan of 512 durations (shuffle-based).
// Phase 2: scatter frame->token map for this window into shared.
// Phase 3: gather 6144 float4, 8 UNCONDITIONAL loads in flight per iter:
//          padding frames load from clamped index 0 (always in-bounds,
//          L1-resident) and the result is replaced by zero with a select.
//          No null pointers, no predicated loads.
// ---------------------------------------------------------------------------
__global__ void __launch_bounds__(NTHR, 4)
lr_fused_kernel(const float4* __restrict__ xs, const int* __restrict__ ds32,
                float4* __restrict__ out) {
    const int b    = blockIdx.x / CHUNKS;
    const int w0   = (blockIdx.x % CHUNKS) * FPB;
    const int tid  = threadIdx.x;
    const int lane = tid & 31;
    const int wid  = tid >> 5;                 // 8 warps

    __shared__ int s_map[FPB];                 // frame -> token (-1 = pad)
    __shared__ int s_warp[8];
    __shared__ int s_off[9];
    __shared__ int s_bad;

    // --- dtype detection sampling (int64 buffer => all odd int32 words are 0;
    //     durations are in [0,4], P(false positive for int32) = 0.2^256) ---
    if (tid == 0) s_bad = 0;
    const int samp = ds32[(2 * (tid * 64) + 1) & 16383];
    if (tid < FPB) s_map[tid] = -1;
    __syncthreads();
    if (samp != 0) atomicOr(&s_bad, 1);
    __syncthreads();
    const bool is64 = (s_bad == 0);

    // --- load 2 durations per thread ---
    int d0, d1;
    if (is64) {
        longlong2 p = ((const longlong2*)ds32)[b * (TT / 2) + tid];
        d0 = (int)p.x; d1 = (int)p.y;
    } else {
        int2 p = ((const int2*)ds32)[b * (TT / 2) + tid];
        d0 = p.x; d1 = p.y;
    }

    // --- hierarchical inclusive scan over 512 ---
    int sum = d0 + d1;
    int incl = sum;
#pragma unroll
    for (int off = 1; off < 32; off <<= 1) {
        int n = __shfl_up_sync(0xFFFFFFFFu, incl, off);
        if (lane >= off) incl += n;
    }
    if (lane == 31) s_warp[wid] = incl;
    __syncthreads();
    if (wid == 0) {
        int w = (lane < 8) ? s_warp[lane] : 0;
#pragma unroll
        for (int off = 1; off < 8; off <<= 1) {
            int n = __shfl_up_sync(0xFFFFFFFFu, w, off);
            if (lane >= off) w += n;
        }
        if (lane < 8) s_off[lane + 1] = w;
        if (lane == 0) s_off[0] = 0;
    }
    __syncthreads();

    const int excl  = incl - sum + s_off[wid]; // exclusive prefix at token 2*tid
    const int total = s_off[8];

    // --- scatter into this block's frame window ---
    const int w1 = w0 + FPB;
    if (total == 0) {
        // all-zero row => durations all 1 => identity map for f < T
        if (tid < FPB) {
            int f = w0 + tid;
            s_map[tid] = (f < TT) ? f : -1;
        }
    } else {
        int st = excl, en = excl + d0;
        int lo = st > w0 ? st : w0;
        int hi = en < w1 ? en : w1;
        for (int f = lo; f < hi; f++) s_map[f - w0] = 2 * tid;
        st = en; en += d1;
        lo = st > w0 ? st : w0;
        hi = en < w1 ? en : w1;
        for (int f = lo; f < hi; f++) s_map[f - w0] = 2 * tid + 1;
    }
    __syncthreads();

    // --- gather: 24 float4 per thread, 8 unconditional loads in flight ---
    const float4* xsb  = xs  + (size_t)b * TT * D4;
    float4*       outb = out + ((size_t)b * MF + w0) * D4;

#pragma unroll
    for (int it = 0; it < ITERS; it++) {
        const int j0 = it * (NTHR * MLP) + tid;

        int  idx[MLP];
        int  off[MLP];
#pragma unroll
        for (int k = 0; k < MLP; k++) {
            const int j = j0 + k * NTHR;       // < 6144
            const int f = j / D4;
            const int c = j - f * D4;
            const int raw = s_map[f];
            idx[k] = raw;
            const int safe = raw < 0 ? 0 : raw;   // clamp: always in-bounds
            off[k] = safe * D4 + c;
        }

        float4 v[MLP];
#pragma unroll
        for (int k = 0; k < MLP; k++)
            v[k] = __ldg(&xsb[off[k]]);           // unconditional LDG.128

#pragma unroll
        for (int k = 0; k < MLP; k++) {
            const bool pad = idx[k] < 0;
            v[k].x = pad ? 0.f : v[k].x;
            v[k].y = pad ? 0.f : v[k].y;
            v[k].z = pad ? 0.f : v[k].z;
            v[k].w = pad ? 0.f : v[k].w;
            outb[j0 + k * NTHR] = v[k];
        }
    }
}

// ---------------------------------------------------------------------------
extern "C" void kernel_launch(void* const* d_in, const int* in_sizes, int n_in,
                              void* d_out, int out_size) {
    // Select pointers by element count (xs: 6,291,456 floats; ds: 16,384).
    const float* xs;
    const int* ds;
    if (in_sizes[0] > in_sizes[1]) {
        xs = (const float*)d_in[0];  ds = (const int*)d_in[1];
    } else {
        xs = (const float*)d_in[1];  ds = (const int*)d_in[0];
    }
    float4* out = (float4*)d_out;

    lr_fused_kernel<<<BB * CHUNKS, NTHR>>>((const float4*)xs, ds, out);
}

// round 7
// speedup vs baseline: 1.3393x; 1.1484x over previous
#include <cuda_runtime.h>

// LengthRegulator (fused single kernel, high-occupancy config):
//   out[b, f, :] = xs[b, searchsorted(cumsum(ds[b]), f, right), :]
//   (0 if f >= total); all-zero ds rows treated as all-ones.
// B=32, T=512, D=384, MAX_FRAMES=2048.

#define BB 32
#define TT 512
#define DD 384
#define MF 2048
#define D4 (DD / 4)            // 96 float4 per frame
#define FPB 32                 // frames per block
#define CHUNKS (MF / FPB)      // 64 chunks per batch
#define NTHR 128               // 4 warps
#define ELEMS (FPB * D4)       // 3072 float4 per block
#define PER_THR (ELEMS / NTHR) // 24
#define MLP 4                  // loads in flight per thread
#define ITERS (PER_THR / MLP)  // 6

// ---------------------------------------------------------------------------
// One block = (batch b, frame window [w0, w0+32)). Grid = 2048 blocks.
// Phase 1: redundant per-batch scan of 512 durations (4 per thread).
// Phase 2: scatter frame->token map for this window into shared.
// Phase 3: gather 3072 float4, 4 unconditional loads in flight, streaming
//          stores (__stcs) so the write-once output doesn't thrash L2.
// ---------------------------------------------------------------------------
__global__ void __launch_bounds__(NTHR)
lr_fused_kernel(const float4* __restrict__ xs, const int* __restrict__ ds32,
                float4* __restrict__ out) {
    const int b    = blockIdx.x / CHUNKS;
    const int w0   = (blockIdx.x % CHUNKS) * FPB;
    const int tid  = threadIdx.x;
    const int lane = tid & 31;
    const int wid  = tid >> 5;                 // 4 warps

    __shared__ int s_map[FPB];                 // frame -> token (-1 = pad)
    __shared__ int s_warp[4];
    __shared__ int s_off[5];
    __shared__ int s_bad;

    // --- dtype detection sampling (int64 buffer => all odd int32 words are 0;
    //     durations are in [0,4], P(false positive for int32) = 0.2^128) ---
    if (tid == 0) s_bad = 0;
    const int samp = ds32[(tid * 256 + 1) & 16383];
    if (tid < FPB) s_map[tid] = -1;
    __syncthreads();
    if (samp != 0) atomicOr(&s_bad, 1);
    __syncthreads();
    const bool is64 = (s_bad == 0);

    // --- load 4 durations per thread (tokens 4*tid .. 4*tid+3) ---
    int d0, d1, d2, d3;
    if (is64) {
        longlong2 p = ((const longlong2*)ds32)[b * (TT / 2) + 2 * tid];
        longlong2 q = ((const longlong2*)ds32)[b * (TT / 2) + 2 * tid + 1];
        d0 = (int)p.x; d1 = (int)p.y; d2 = (int)q.x; d3 = (int)q.y;
    } else {
        int4 p = ((const int4*)ds32)[b * (TT / 4) + tid];
        d0 = p.x; d1 = p.y; d2 = p.z; d3 = p.w;
    }

    // --- hierarchical inclusive scan over 512 (4 per thread) ---
    const int sum4 = d0 + d1 + d2 + d3;
    int incl = sum4;
#pragma unroll
    for (int off = 1; off < 32; off <<= 1) {
        int n = __shfl_up_sync(0xFFFFFFFFu, incl, off);
        if (lane >= off) incl += n;
    }
    if (lane == 31) s_warp[wid] = incl;
    __syncthreads();
    if (wid == 0) {
        int w = (lane < 4) ? s_warp[lane] : 0;
#pragma unroll
        for (int off = 1; off < 4; off <<= 1) {
            int n = __shfl_up_sync(0xFFFFFFFFu, w, off);
            if (lane >= off) w += n;
        }
        if (lane < 4) s_off[lane + 1] = w;
        if (lane == 0) s_off[0] = 0;
    }
    __syncthreads();

    int excl = incl - sum4 + s_off[wid];       // exclusive prefix at token 4*tid
    const int total = s_off[4];

    // --- scatter into this block's frame window [w0, w1) ---
    const int w1 = w0 + FPB;
    if (total == 0) {
        // all-zero row => durations all 1 => identity map for f < T
        if (tid < FPB) {
            int f = w0 + tid;
            s_map[tid] = (f < TT) ? f : -1;
        }
    } else {
        int dd[4] = {d0, d1, d2, d3};
#pragma unroll
        for (int q = 0; q < 4; q++) {
            const int st = excl;
            const int en = excl + dd[q];
            excl = en;
            int lo = st > w0 ? st : w0;
            int hi = en < w1 ? en : w1;
            for (int f = lo; f < hi; f++) s_map[f - w0] = 4 * tid + q;
        }
    }
    __syncthreads();

    // --- gather: 24 float4 per thread, 4 unconditional loads in flight ---
    const float4* xsb  = xs  + (size_t)b * TT * D4;
    float4*       outb = out + ((size_t)b * MF + w0) * D4;

#pragma unroll
    for (int it = 0; it < ITERS; it++) {
        const int j0 = it * (NTHR * MLP) + tid;

        int idx[MLP];
        int off[MLP];
#pragma unroll
        for (int k = 0; k < MLP; k++) {
            const int j = j0 + k * NTHR;       // < 3072
            const int f = j / D4;
            const int c = j - f * D4;
            const int raw = s_map[f];
            idx[k] = raw;
            const int safe = raw < 0 ? 0 : raw;   // clamp: always in-bounds
            off[k] = safe * D4 + c;
        }

        float4 v[MLP];
#pragma unroll
        for (int k = 0; k < MLP; k++)
            v[k] = __ldg(&xsb[off[k]]);           // unconditional LDG.128

#pragma unroll
        for (int k = 0; k < MLP; k++) {
            const bool pad = idx[k] < 0;
            v[k].x = pad ? 0.f : v[k].x;
            v[k].y = pad ? 0.f : v[k].y;
            v[k].z = pad ? 0.f : v[k].z;
            v[k].w = pad ? 0.f : v[k].w;
            __stcs(&outb[j0 + k * NTHR], v[k]);   // streaming store
        }
    }
}

// ---------------------------------------------------------------------------
extern "C" void kernel_launch(void* const* d_in, const int* in_sizes, int n_in,
                              void* d_out, int out_size) {
    // Select pointers by element count (xs: 6,291,456 floats; ds: 16,384).
    const float* xs;
    const int* ds;
    if (in_sizes[0] > in_sizes[1]) {
        xs = (const float*)d_in[0];  ds = (const int*)d_in[1];
    } else {
        xs = (const float*)d_in[1];  ds = (const int*)d_in[0];
    }
    float4* out = (float4*)d_out;

    lr_fused_kernel<<<BB * CHUNKS, NTHR>>>((const float4*)xs, ds, out);
}

// round 8
// speedup vs baseline: 1.4885x; 1.1115x over previous
#include <cuda_runtime.h>

// LengthRegulator, two-kernel form:
//   out[b, f, :] = xs[b, searchsorted(cumsum(ds[b]), f, right), :]
//   (0 if f >= total); all-zero ds rows treated as all-ones.
// B=32, T=512, D=384, MAX_FRAMES=2048.

#define BB 32
#define TT 512
#define DD 384
#define MF 2048
#define D4 (DD / 4)      // 96 float4 per frame
#define UNROLL 4
#define GTHREADS 256

// Frame -> source-token index map; -1 means padding (write zeros).
__device__ int g_idx[BB * MF];

// ---------------------------------------------------------------------------
// Kernel A: per-batch inclusive scan (shuffle-based, 3 barriers total) +
// scatter frame->token map. One block per batch, 128 threads, 4 tokens each.
// ds dtype (int32 vs int64) detected at runtime: durations are in [0,4], so
// an int64 buffer has every odd int32 word == 0. P(false positive) = 0.2^128.
// ---------------------------------------------------------------------------
__global__ void __launch_bounds__(128) lr_scan_kernel(const int* __restrict__ ds32) {
    const int b    = blockIdx.x;
    const int tid  = threadIdx.x;
    const int lane = tid & 31;
    const int wid  = tid >> 5;                 // 4 warps

    __shared__ int s_warp[4];
    __shared__ int s_off[5];
    __shared__ int s_bad;

    if (tid == 0) s_bad = 0;
    const int samp = ds32[(tid * 256 + 1) & 16383];  // odd words only
    // init this batch's g_idx to -1 (512 int4 stores across 128 threads)
#pragma unroll
    for (int k = 0; k < 4; k++)
        ((int4*)g_idx)[b * (MF / 4) + tid + k * 128] = make_int4(-1, -1, -1, -1);
    __syncthreads();
    if (samp != 0) atomicOr(&s_bad, 1);
    __syncthreads();
    const bool is64 = (s_bad == 0);

    // --- load 4 durations per thread (tokens 4*tid .. 4*tid+3) ---
    int d0, d1, d2, d3;
    if (is64) {
        longlong2 p = ((const longlong2*)ds32)[b * (TT / 2) + 2 * tid];
        longlong2 q = ((const longlong2*)ds32)[b * (TT / 2) + 2 * tid + 1];
        d0 = (int)p.x; d1 = (int)p.y; d2 = (int)q.x; d3 = (int)q.y;
    } else {
        int4 p = ((const int4*)ds32)[b * (TT / 4) + tid];
        d0 = p.x; d1 = p.y; d2 = p.z; d3 = p.w;
    }

    // --- hierarchical inclusive scan over 512 (4 per thread) ---
    const int sum4 = d0 + d1 + d2 + d3;
    int incl = sum4;
#pragma unroll
    for (int off = 1; off < 32; off <<= 1) {
        int n = __shfl_up_sync(0xFFFFFFFFu, incl, off);
        if (lane >= off) incl += n;
    }
    if (lane == 31) s_warp[wid] = incl;
    __syncthreads();
    if (wid == 0) {
        int w = (lane < 4) ? s_warp[lane] : 0;
#pragma unroll
        for (int off = 1; off < 4; off <<= 1) {
            int n = __shfl_up_sync(0xFFFFFFFFu, w, off);
            if (lane >= off) w += n;
        }
        if (lane < 4) s_off[lane + 1] = w;
        if (lane == 0) s_off[0] = 0;
    }
    __syncthreads();

    int excl = incl - sum4 + s_off[wid];       // exclusive prefix at token 4*tid
    const int total = s_off[4];

    if (total == 0) {
        // all-zero row => durations all 1 => identity map for f < T
#pragma unroll
        for (int k = 0; k < 4; k++)
            g_idx[b * MF + 4 * tid + k] = 4 * tid + k;
    } else {
        int dd[4] = {d0, d1, d2, d3};
#pragma unroll
        for (int q = 0; q < 4; q++) {
            const int en = excl + dd[q];
            for (int f = excl; f < en; f++)
                g_idx[b * MF + f] = 4 * tid + q;
            excl = en;
        }
    }
}

// ---------------------------------------------------------------------------
// Kernel B: bandwidth mover (R3 structure + streaming stores + clamped
// unconditional loads). 4 float4 per thread; 6144 blocks x 256 threads exact.
// ---------------------------------------------------------------------------
__global__ void __launch_bounds__(GTHREADS)
lr_gather_kernel(const float4* __restrict__ xs, float4* __restrict__ out) {
    const int base  = blockIdx.x * (GTHREADS * UNROLL) + threadIdx.x;
    const int per_b = MF * D4;

    int idx[UNROLL];
    int srcoff[UNROLL];
#pragma unroll
    for (int k = 0; k < UNROLL; k++) {
        const int i   = base + k * GTHREADS;
        const int b   = i / per_b;
        const int rem = i - b * per_b;
        const int f   = rem / D4;
        const int c   = rem - f * D4;
        const int raw = g_idx[b * MF + f];      // L1-resident map
        idx[k] = raw;
        const int safe = raw < 0 ? 0 : raw;     // clamp: always in-bounds
        srcoff[k] = (b * TT + safe) * D4 + c;
    }

    float4 v[UNROLL];
#pragma unroll
    for (int k = 0; k < UNROLL; k++)
        v[k] = __ldg(&xs[srcoff[k]]);           // unconditional LDG.128

#pragma unroll
    for (int k = 0; k < UNROLL; k++) {
        const bool pad = idx[k] < 0;
        v[k].x = pad ? 0.f : v[k].x;
        v[k].y = pad ? 0.f : v[k].y;
        v[k].z = pad ? 0.f : v[k].z;
        v[k].w = pad ? 0.f : v[k].w;
        __stcs(&out[base + k * GTHREADS], v[k]); // streaming store
    }
}

// ---------------------------------------------------------------------------
extern "C" void kernel_launch(void* const* d_in, const int* in_sizes, int n_in,
                              void* d_out, int out_size) {
    // Select pointers by element count (xs: 6,291,456 floats; ds: 16,384).
    const float* xs;
    const int* ds;
    if (in_sizes[0] > in_sizes[1]) {
        xs = (const float*)d_in[0];  ds = (const int*)d_in[1];
    } else {
        xs = (const float*)d_in[1];  ds = (const int*)d_in[0];
    }
    float4* out = (float4*)d_out;

    lr_scan_kernel<<<BB, 128>>>(ds);

    const int total4 = BB * MF * D4;                     // 6,291,456
    const int blocks = total4 / (GTHREADS * UNROLL);     // 6144 exact
    lr_gather_kernel<<<blocks, GTHREADS>>>((const float4*)xs, out);
}